// round 10
// baseline (speedup 1.0000x reference)
#include <cuda_runtime.h>
#include <math.h>

#define C 128
#define CV 32            // C/4 float4 per row
#define HID 8
#define NB 16

#define RED_BLOCKS 592   // one full wave at ~50 regs (4 blocks/SM)
#define APPLY_BLOCKS 1184

// Scratch (no allocations allowed). Zero-initialized at load; mlp_kernel
// re-zeroes g_sums/g_counts after consuming them -> every call starts clean.
__device__ float g_sums[NB][C];
__device__ float g_counts[NB];
__device__ float g_gate[NB][C];

// ---------------------------------------------------------------------------
// 1) segment sum, GRID-STRIDE (key change): all warps advance in lockstep
//    through the address space, so the whole chip drains together — no
//    chunk-tail underutilization (B300 multi-CTA spread model). Unroll 8
//    with front-batched independent loads (MLP_p1=8), register accumulation,
//    flush on segment change (<=16 flushes/warp, sorted bidx).
// ---------------------------------------------------------------------------
__global__ __launch_bounds__(256) void reduce_kernel(
    const float4* __restrict__ x, const int* __restrict__ bidx, int n)
{
    int lane  = threadIdx.x & 31;
    int gwarp = (blockIdx.x * blockDim.x + threadIdx.x) >> 5;
    int nwarps = (gridDim.x * blockDim.x) >> 5;

    float4 accA = make_float4(0.f, 0.f, 0.f, 0.f);
    float4 accB = make_float4(0.f, 0.f, 0.f, 0.f);
    float cnt = 0.f;
    int cur_b = -1;

    auto flush = [&]() {
        float* dst = &g_sums[cur_b][lane * 4];
        atomicAdd(dst + 0, accA.x + accB.x);
        atomicAdd(dst + 1, accA.y + accB.y);
        atomicAdd(dst + 2, accA.z + accB.z);
        atomicAdd(dst + 3, accA.w + accB.w);
        if (lane == 0) atomicAdd(&g_counts[cur_b], cnt);
    };
    auto consumeA = [&](int b, const float4& v) {
        if (b != cur_b) {                 // rare: <=15 boundaries in sequence
            if (cur_b >= 0) flush();
            cur_b = b;
            accA = make_float4(0.f, 0.f, 0.f, 0.f);
            accB = make_float4(0.f, 0.f, 0.f, 0.f);
            cnt = 0.f;
        }
        accA.x += v.x; accA.y += v.y; accA.z += v.z; accA.w += v.w;
        cnt += 1.0f;                      // only lane 0's value is used
    };
    auto consumeB = [&](int b, const float4& v) {
        if (b != cur_b) {
            if (cur_b >= 0) flush();
            cur_b = b;
            accA = make_float4(0.f, 0.f, 0.f, 0.f);
            accB = make_float4(0.f, 0.f, 0.f, 0.f);
            cnt = 0.f;
        }
        accB.x += v.x; accB.y += v.y; accB.z += v.z; accB.w += v.w;
        cnt += 1.0f;
    };

    int r = gwarp;
    // main loop: 8 independent rows in flight per warp, stride = nwarps
    for (; r + 7 * nwarps < n; r += 8 * nwarps) {
        int r0 = r;
        int r1 = r + nwarps;
        int r2 = r + 2 * nwarps;
        int r3 = r + 3 * nwarps;
        int r4 = r + 4 * nwarps;
        int r5 = r + 5 * nwarps;
        int r6 = r + 6 * nwarps;
        int r7 = r + 7 * nwarps;
        int b0 = bidx[r0];
        int b1 = bidx[r1];
        int b2 = bidx[r2];
        int b3 = bidx[r3];
        int b4 = bidx[r4];
        int b5 = bidx[r5];
        int b6 = bidx[r6];
        int b7 = bidx[r7];
        float4 v0 = x[(size_t)r0 * CV + lane];
        float4 v1 = x[(size_t)r1 * CV + lane];
        float4 v2 = x[(size_t)r2 * CV + lane];
        float4 v3 = x[(size_t)r3 * CV + lane];
        float4 v4 = x[(size_t)r4 * CV + lane];
        float4 v5 = x[(size_t)r5 * CV + lane];
        float4 v6 = x[(size_t)r6 * CV + lane];
        float4 v7 = x[(size_t)r7 * CV + lane];
        consumeA(b0, v0);
        consumeB(b1, v1);
        consumeA(b2, v2);
        consumeB(b3, v3);
        consumeA(b4, v4);
        consumeB(b5, v5);
        consumeA(b6, v6);
        consumeB(b7, v7);
    }
    // remainder
    for (; r < n; r += nwarps) {
        int b = bidx[r];
        float4 v = x[(size_t)r * CV + lane];
        consumeA(b, v);
    }
    if (cur_b >= 0) flush();
}

// ---------------------------------------------------------------------------
// 2) tiny MLP: 256 threads, weights cooperatively preloaded (vectorized) so
//    GMEM latency is paid once, not 128x serially. Re-zeroes accumulators.
// ---------------------------------------------------------------------------
__global__ __launch_bounds__(256) void mlp_kernel(
    const float* __restrict__ W1, const float* __restrict__ b1,
    const float* __restrict__ W2, const float* __restrict__ b2)
{
    __shared__ float sW1[C * HID];     // 1024
    __shared__ float sW2[HID * C];     // 1024
    __shared__ float s_b1[HID];
    __shared__ float s_b2[C];
    __shared__ float s_mean[NB][C];    // 2048
    __shared__ float s_h[NB][HID];     // 128

    int t = threadIdx.x;  // 0..255

    for (int i = t; i < (C * HID) / 4; i += 256) {
        ((float4*)sW1)[i] = ((const float4*)W1)[i];
        ((float4*)sW2)[i] = ((const float4*)W2)[i];
    }
    if (t < HID) s_b1[t] = b1[t];
    if (t < C)   s_b2[t] = b2[t];
    for (int i = t; i < NB * C; i += 256) {
        int b = i / C;
        float cn = fmaxf(g_counts[b], 1.0f);
        ((float*)s_mean)[i] = ((const float*)g_sums)[i] / cn;
    }
    __syncthreads();

    // reset accumulators for the next invocation
    for (int i = t; i < NB * C; i += 256) ((float*)g_sums)[i] = 0.0f;
    if (t < NB) g_counts[t] = 0.0f;

    if (t < NB * HID) {                // 128 outputs: h[b][j]
        int b = t / HID, j = t % HID;
        float acc = s_b1[j];
        #pragma unroll 8
        for (int c = 0; c < C; c++) acc += s_mean[b][c] * sW1[c * HID + j];
        s_h[b][j] = fmaxf(acc, 0.0f);
    }
    __syncthreads();

    if (t < C) {                       // gate column c = t
        int c = t;
        float w2c[HID];
        #pragma unroll
        for (int j = 0; j < HID; j++) w2c[j] = sW2[j * C + c];
        float bias = s_b2[c];
        for (int b = 0; b < NB; b++) {
            float acc = bias;
            #pragma unroll
            for (int j = 0; j < HID; j++) acc += s_h[b][j] * w2c[j];
            g_gate[b][c] = 1.0f / (1.0f + expf(-acc));
        }
    }
}

// ---------------------------------------------------------------------------
// 3) apply gate (measured 78.8us, at ceiling): grid-stride ascending, plain
//    loads/stores, x2 unroll with front-batched loads. Unchanged.
// ---------------------------------------------------------------------------
__global__ __launch_bounds__(256) void apply_kernel(
    const float4* __restrict__ x, const int* __restrict__ bidx,
    float4* __restrict__ out, int n)
{
    __shared__ float4 s_gate[NB][CV];  // 8 KB
    for (int i = threadIdx.x; i < NB * CV; i += blockDim.x)
        ((float4*)s_gate)[i] = ((const float4*)g_gate)[i];
    __syncthreads();

    int lane = threadIdx.x & 31;
    int gwarp = (blockIdx.x * blockDim.x + threadIdx.x) >> 5;
    int nwarps = (gridDim.x * blockDim.x) >> 5;

    int r = gwarp;
    for (; r + nwarps < n; r += 2 * nwarps) {
        int r2 = r + nwarps;
        int b0 = bidx[r];
        int b1 = bidx[r2];
        float4 v0 = x[(size_t)r  * CV + lane];
        float4 v1 = x[(size_t)r2 * CV + lane];
        float4 g0 = s_gate[b0][lane];
        float4 g1 = s_gate[b1][lane];
        v0.x *= g0.x; v0.y *= g0.y; v0.z *= g0.z; v0.w *= g0.w;
        v1.x *= g1.x; v1.y *= g1.y; v1.z *= g1.z; v1.w *= g1.w;
        out[(size_t)r  * CV + lane] = v0;
        out[(size_t)r2 * CV + lane] = v1;
    }
    if (r < n) {
        int b = bidx[r];
        float4 v = x[(size_t)r * CV + lane];
        float4 g = s_gate[b][lane];
        v.x *= g.x; v.y *= g.y; v.z *= g.z; v.w *= g.w;
        out[(size_t)r * CV + lane] = v;
    }
}

// ---------------------------------------------------------------------------
extern "C" void kernel_launch(void* const* d_in, const int* in_sizes, int n_in,
                              void* d_out, int out_size)
{
    const float* x    = (const float*)d_in[0];
    const int*   bidx = (const int*)d_in[1];
    const float* W1   = (const float*)d_in[2];
    const float* b1   = (const float*)d_in[3];
    const float* W2   = (const float*)d_in[4];
    const float* b2   = (const float*)d_in[5];
    float* out = (float*)d_out;

    int n = in_sizes[1];  // number of rows (batch_idx has N entries)

    reduce_kernel<<<RED_BLOCKS, 256>>>((const float4*)x, bidx, n);
    mlp_kernel<<<1, 256>>>(W1, b1, W2, b2);
    apply_kernel<<<APPLY_BLOCKS, 256>>>((const float4*)x, bidx, (float4*)out, n);
}

// round 11
// speedup vs baseline: 2.0238x; 2.0238x over previous
#include <cuda_runtime.h>
#include <math.h>

#define C 128
#define CV 32            // C/4 float4 per row
#define HID 8
#define NB 16

#define RED_BLOCKS 592
#define RED_TILE 128     // rows per tile; block strides over tiles
#define APPLY_BLOCKS 1184

// Scratch (no allocations allowed). Zero-initialized at load; mlp_kernel
// re-zeroes g_sums/g_counts after consuming them -> every call starts clean.
__device__ float g_sums[NB][C];
__device__ float g_counts[NB];
__device__ float g_gate[NB][C];

// ---------------------------------------------------------------------------
// 1) segment sum, TILE-STRIDED: block b handles contiguous 128-row tiles
//    b, b+gridDim, ... so all blocks advance in near-lockstep (no chunk-tail
//    drain), while WITHIN a tile sampling stays contiguous -> segment-change
//    flushes stay rare (~6-7 per warp total). Inner loop = R6's proven
//    unroll-8 front-batched form (MLP_p1 = 8), register accumulation.
// ---------------------------------------------------------------------------
__global__ __launch_bounds__(256) void reduce_kernel(
    const float4* __restrict__ x, const int* __restrict__ bidx, int n)
{
    int warp = threadIdx.x >> 5;
    int lane = threadIdx.x & 31;
    int ntiles = (n + RED_TILE - 1) / RED_TILE;

    float4 accA = make_float4(0.f, 0.f, 0.f, 0.f);
    float4 accB = make_float4(0.f, 0.f, 0.f, 0.f);
    float cnt = 0.f;
    int cur_b = -1;

    for (int t = blockIdx.x; t < ntiles; t += gridDim.x) {
        int t0   = t * RED_TILE;
        int tend = t0 + RED_TILE;
        if (tend > n) tend = n;

        int r = t0 + warp;
        // full-tile fast path: 16 samples per warp = two unroll-8 groups
        for (; r + 56 < tend; r += 64) {
            int   b0 = bidx[r];
            int   b1 = bidx[r + 8];
            int   b2 = bidx[r + 16];
            int   b3 = bidx[r + 24];
            int   b4 = bidx[r + 32];
            int   b5 = bidx[r + 40];
            int   b6 = bidx[r + 48];
            int   b7 = bidx[r + 56];
            float4 v0 = x[(size_t)(r)      * CV + lane];
            float4 v1 = x[(size_t)(r + 8)  * CV + lane];
            float4 v2 = x[(size_t)(r + 16) * CV + lane];
            float4 v3 = x[(size_t)(r + 24) * CV + lane];
            float4 v4 = x[(size_t)(r + 32) * CV + lane];
            float4 v5 = x[(size_t)(r + 40) * CV + lane];
            float4 v6 = x[(size_t)(r + 48) * CV + lane];
            float4 v7 = x[(size_t)(r + 56) * CV + lane];

            #define RK_CONSUME(BB, VV, ACC)                                   \
                if (BB != cur_b) {   /* rare: segment boundary */             \
                    if (cur_b >= 0) {                                         \
                        float* dst = &g_sums[cur_b][lane * 4];                \
                        atomicAdd(dst + 0, accA.x + accB.x);                  \
                        atomicAdd(dst + 1, accA.y + accB.y);                  \
                        atomicAdd(dst + 2, accA.z + accB.z);                  \
                        atomicAdd(dst + 3, accA.w + accB.w);                  \
                        if (lane == 0) atomicAdd(&g_counts[cur_b], cnt);      \
                    }                                                         \
                    cur_b = BB;                                               \
                    accA = make_float4(0.f, 0.f, 0.f, 0.f);                   \
                    accB = make_float4(0.f, 0.f, 0.f, 0.f);                   \
                    cnt = 0.f;                                                \
                }                                                             \
                ACC.x += VV.x; ACC.y += VV.y; ACC.z += VV.z; ACC.w += VV.w;   \
                cnt += 1.0f;

            RK_CONSUME(b0, v0, accA)
            RK_CONSUME(b1, v1, accB)
            RK_CONSUME(b2, v2, accA)
            RK_CONSUME(b3, v3, accB)
            RK_CONSUME(b4, v4, accA)
            RK_CONSUME(b5, v5, accB)
            RK_CONSUME(b6, v6, accA)
            RK_CONSUME(b7, v7, accB)
        }
        // tile remainder (last partial tile only)
        for (; r < tend; r += 8) {
            int b = bidx[r];
            float4 v = x[(size_t)r * CV + lane];
            RK_CONSUME(b, v, accA)
        }
    }

    if (cur_b >= 0) {
        float* dst = &g_sums[cur_b][lane * 4];
        atomicAdd(dst + 0, accA.x + accB.x);
        atomicAdd(dst + 1, accA.y + accB.y);
        atomicAdd(dst + 2, accA.z + accB.z);
        atomicAdd(dst + 3, accA.w + accB.w);
        if (lane == 0) atomicAdd(&g_counts[cur_b], cnt);
    }
}

// ---------------------------------------------------------------------------
// 2) tiny MLP: 256 threads, weights cooperatively preloaded (vectorized).
//    Re-zeroes accumulators for the next invocation. (~3us measured)
// ---------------------------------------------------------------------------
__global__ __launch_bounds__(256) void mlp_kernel(
    const float* __restrict__ W1, const float* __restrict__ b1,
    const float* __restrict__ W2, const float* __restrict__ b2)
{
    __shared__ float sW1[C * HID];
    __shared__ float sW2[HID * C];
    __shared__ float s_b1[HID];
    __shared__ float s_b2[C];
    __shared__ float s_mean[NB][C];
    __shared__ float s_h[NB][HID];

    int t = threadIdx.x;  // 0..255

    for (int i = t; i < (C * HID) / 4; i += 256) {
        ((float4*)sW1)[i] = ((const float4*)W1)[i];
        ((float4*)sW2)[i] = ((const float4*)W2)[i];
    }
    if (t < HID) s_b1[t] = b1[t];
    if (t < C)   s_b2[t] = b2[t];
    for (int i = t; i < NB * C; i += 256) {
        int b = i / C;
        float cn = fmaxf(g_counts[b], 1.0f);
        ((float*)s_mean)[i] = ((const float*)g_sums)[i] / cn;
    }
    __syncthreads();

    // reset accumulators for the next invocation
    for (int i = t; i < NB * C; i += 256) ((float*)g_sums)[i] = 0.0f;
    if (t < NB) g_counts[t] = 0.0f;

    if (t < NB * HID) {                // 128 outputs: h[b][j]
        int b = t / HID, j = t % HID;
        float acc = s_b1[j];
        #pragma unroll 8
        for (int c = 0; c < C; c++) acc += s_mean[b][c] * sW1[c * HID + j];
        s_h[b][j] = fmaxf(acc, 0.0f);
    }
    __syncthreads();

    if (t < C) {                       // gate column c = t
        int c = t;
        float w2c[HID];
        #pragma unroll
        for (int j = 0; j < HID; j++) w2c[j] = sW2[j * C + c];
        float bias = s_b2[c];
        for (int b = 0; b < NB; b++) {
            float acc = bias;
            #pragma unroll
            for (int j = 0; j < HID; j++) acc += s_h[b][j] * w2c[j];
            g_gate[b][c] = 1.0f / (1.0f + expf(-acc));
        }
    }
}

// ---------------------------------------------------------------------------
// 3) apply gate (measured 78.8us, at ceiling): grid-stride ascending, plain
//    loads/stores, x2 unroll with front-batched loads. Unchanged.
// ---------------------------------------------------------------------------
__global__ __launch_bounds__(256) void apply_kernel(
    const float4* __restrict__ x, const int* __restrict__ bidx,
    float4* __restrict__ out, int n)
{
    __shared__ float4 s_gate[NB][CV];  // 8 KB
    for (int i = threadIdx.x; i < NB * CV; i += blockDim.x)
        ((float4*)s_gate)[i] = ((const float4*)g_gate)[i];
    __syncthreads();

    int lane = threadIdx.x & 31;
    int gwarp = (blockIdx.x * blockDim.x + threadIdx.x) >> 5;
    int nwarps = (gridDim.x * blockDim.x) >> 5;

    int r = gwarp;
    for (; r + nwarps < n; r += 2 * nwarps) {
        int r2 = r + nwarps;
        int b0 = bidx[r];
        int b1 = bidx[r2];
        float4 v0 = x[(size_t)r  * CV + lane];
        float4 v1 = x[(size_t)r2 * CV + lane];
        float4 g0 = s_gate[b0][lane];
        float4 g1 = s_gate[b1][lane];
        v0.x *= g0.x; v0.y *= g0.y; v0.z *= g0.z; v0.w *= g0.w;
        v1.x *= g1.x; v1.y *= g1.y; v1.z *= g1.z; v1.w *= g1.w;
        out[(size_t)r  * CV + lane] = v0;
        out[(size_t)r2 * CV + lane] = v1;
    }
    if (r < n) {
        int b = bidx[r];
        float4 v = x[(size_t)r * CV + lane];
        float4 g = s_gate[b][lane];
        v.x *= g.x; v.y *= g.y; v.z *= g.z; v.w *= g.w;
        out[(size_t)r * CV + lane] = v;
    }
}

// ---------------------------------------------------------------------------
extern "C" void kernel_launch(void* const* d_in, const int* in_sizes, int n_in,
                              void* d_out, int out_size)
{
    const float* x    = (const float*)d_in[0];
    const int*   bidx = (const int*)d_in[1];
    const float* W1   = (const float*)d_in[2];
    const float* b1   = (const float*)d_in[3];
    const float* W2   = (const float*)d_in[4];
    const float* b2   = (const float*)d_in[5];
    float* out = (float*)d_out;

    int n = in_sizes[1];  // number of rows (batch_idx has N entries)

    reduce_kernel<<<RED_BLOCKS, 256>>>((const float4*)x, bidx, n);
    mlp_kernel<<<1, 256>>>(W1, b1, W2, b2);
    apply_kernel<<<APPLY_BLOCKS, 256>>>((const float4*)x, bidx, (float4*)out, n);
}

// round 12
// speedup vs baseline: 3.6866x; 1.8216x over previous
#include <cuda_runtime.h>
#include <math.h>

#define C 128
#define CV 32            // C/4 float4 per row
#define HID 8
#define NB 16

#define RED_BLOCKS 592   // R6-measured optimum (56.6us, 38 regs)
#define APPLY_BLOCKS 1184

// Scratch (no allocations allowed). Zero-initialized at load; mlp_kernel
// re-zeroes g_sums/g_counts after consuming them -> every call starts clean.
__device__ float g_sums[NB][C];
__device__ float g_counts[NB];
__device__ float g_gate[NB][C];

// ---------------------------------------------------------------------------
// 1) segment sum — EXACT R6 form (measured 56.6us, regs=38).
//    Block owns contiguous rows [row0,row1); bidx sorted, 16 segments ->
//    block spans few segments; binary-search boundaries (hoisted OUT of the
//    hot loop), then stream each segment with a branchless load/FADD loop
//    (unroll 8, two accumulators). Low regs => good occupancy => BW.
// ---------------------------------------------------------------------------
__device__ __forceinline__ int lower_bound_idx(const int* __restrict__ bidx,
                                               int lo, int hi, int val) {
    while (lo < hi) {
        int mid = (lo + hi) >> 1;
        if (bidx[mid] < val) lo = mid + 1; else hi = mid;
    }
    return lo;
}

__global__ __launch_bounds__(256) void reduce_kernel(
    const float4* __restrict__ x, const int* __restrict__ bidx,
    int n, int rows_per_block)
{
    int row0 = blockIdx.x * rows_per_block;
    int row1 = row0 + rows_per_block;
    if (row1 > n) row1 = n;
    if (row0 >= row1) return;

    int warp = threadIdx.x >> 5;
    int lane = threadIdx.x & 31;

    int b_first = bidx[row0];
    int b_last  = bidx[row1 - 1];

    int seg_start = row0;
    for (int b = b_first; b <= b_last; b++) {
        int seg_end = (b == b_last) ? row1
                    : lower_bound_idx(bidx, seg_start, row1, b + 1);

        float4 accA = make_float4(0.f, 0.f, 0.f, 0.f);
        float4 accB = make_float4(0.f, 0.f, 0.f, 0.f);

        int r = seg_start + warp;
        for (; r + 56 < seg_end; r += 64) {
            float4 v0 = x[(size_t)(r)      * CV + lane];
            float4 v1 = x[(size_t)(r + 8)  * CV + lane];
            float4 v2 = x[(size_t)(r + 16) * CV + lane];
            float4 v3 = x[(size_t)(r + 24) * CV + lane];
            float4 v4 = x[(size_t)(r + 32) * CV + lane];
            float4 v5 = x[(size_t)(r + 40) * CV + lane];
            float4 v6 = x[(size_t)(r + 48) * CV + lane];
            float4 v7 = x[(size_t)(r + 56) * CV + lane];
            accA.x += v0.x; accA.y += v0.y; accA.z += v0.z; accA.w += v0.w;
            accB.x += v1.x; accB.y += v1.y; accB.z += v1.z; accB.w += v1.w;
            accA.x += v2.x; accA.y += v2.y; accA.z += v2.z; accA.w += v2.w;
            accB.x += v3.x; accB.y += v3.y; accB.z += v3.z; accB.w += v3.w;
            accA.x += v4.x; accA.y += v4.y; accA.z += v4.z; accA.w += v4.w;
            accB.x += v5.x; accB.y += v5.y; accB.z += v5.z; accB.w += v5.w;
            accA.x += v6.x; accA.y += v6.y; accA.z += v6.z; accA.w += v6.w;
            accB.x += v7.x; accB.y += v7.y; accB.z += v7.z; accB.w += v7.w;
        }
        for (; r < seg_end; r += 8) {
            float4 v = x[(size_t)r * CV + lane];
            accA.x += v.x; accA.y += v.y; accA.z += v.z; accA.w += v.w;
        }

        int seg_len = seg_end - seg_start;
        if (seg_len > 0) {
            float* dst = &g_sums[b][lane * 4];
            atomicAdd(dst + 0, accA.x + accB.x);
            atomicAdd(dst + 1, accA.y + accB.y);
            atomicAdd(dst + 2, accA.z + accB.z);
            atomicAdd(dst + 3, accA.w + accB.w);
            if (lane == 0 && warp == 0)
                atomicAdd(&g_counts[b], (float)seg_len);
        }
        seg_start = seg_end;
    }
}

// ---------------------------------------------------------------------------
// 2) tiny MLP (R9 fast version, ~3-4us): 256 threads, weights cooperatively
//    preloaded vectorized. Re-zeroes accumulators for the next invocation.
// ---------------------------------------------------------------------------
__global__ __launch_bounds__(256) void mlp_kernel(
    const float* __restrict__ W1, const float* __restrict__ b1,
    const float* __restrict__ W2, const float* __restrict__ b2)
{
    __shared__ float sW1[C * HID];
    __shared__ float sW2[HID * C];
    __shared__ float s_b1[HID];
    __shared__ float s_b2[C];
    __shared__ float s_mean[NB][C];
    __shared__ float s_h[NB][HID];

    int t = threadIdx.x;  // 0..255

    for (int i = t; i < (C * HID) / 4; i += 256) {
        ((float4*)sW1)[i] = ((const float4*)W1)[i];
        ((float4*)sW2)[i] = ((const float4*)W2)[i];
    }
    if (t < HID) s_b1[t] = b1[t];
    if (t < C)   s_b2[t] = b2[t];
    for (int i = t; i < NB * C; i += 256) {
        int b = i / C;
        float cn = fmaxf(g_counts[b], 1.0f);
        ((float*)s_mean)[i] = ((const float*)g_sums)[i] / cn;
    }
    __syncthreads();

    // reset accumulators for the next invocation
    for (int i = t; i < NB * C; i += 256) ((float*)g_sums)[i] = 0.0f;
    if (t < NB) g_counts[t] = 0.0f;

    if (t < NB * HID) {                // 128 outputs: h[b][j]
        int b = t / HID, j = t % HID;
        float acc = s_b1[j];
        #pragma unroll 8
        for (int c = 0; c < C; c++) acc += s_mean[b][c] * sW1[c * HID + j];
        s_h[b][j] = fmaxf(acc, 0.0f);
    }
    __syncthreads();

    if (t < C) {                       // gate column c = t
        int c = t;
        float w2c[HID];
        #pragma unroll
        for (int j = 0; j < HID; j++) w2c[j] = sW2[j * C + c];
        float bias = s_b2[c];
        for (int b = 0; b < NB; b++) {
            float acc = bias;
            #pragma unroll
            for (int j = 0; j < HID; j++) acc += s_h[b][j] * w2c[j];
            g_gate[b][c] = 1.0f / (1.0f + expf(-acc));
        }
    }
}

// ---------------------------------------------------------------------------
// 3) apply gate (measured 77-78.8us, at LTS ceiling): grid-stride ascending,
//    plain loads/stores, x2 unroll with front-batched loads. Unchanged.
// ---------------------------------------------------------------------------
__global__ __launch_bounds__(256) void apply_kernel(
    const float4* __restrict__ x, const int* __restrict__ bidx,
    float4* __restrict__ out, int n)
{
    __shared__ float4 s_gate[NB][CV];  // 8 KB
    for (int i = threadIdx.x; i < NB * CV; i += blockDim.x)
        ((float4*)s_gate)[i] = ((const float4*)g_gate)[i];
    __syncthreads();

    int lane = threadIdx.x & 31;
    int gwarp = (blockIdx.x * blockDim.x + threadIdx.x) >> 5;
    int nwarps = (gridDim.x * blockDim.x) >> 5;

    int r = gwarp;
    for (; r + nwarps < n; r += 2 * nwarps) {
        int r2 = r + nwarps;
        int b0 = bidx[r];
        int b1 = bidx[r2];
        float4 v0 = x[(size_t)r  * CV + lane];
        float4 v1 = x[(size_t)r2 * CV + lane];
        float4 g0 = s_gate[b0][lane];
        float4 g1 = s_gate[b1][lane];
        v0.x *= g0.x; v0.y *= g0.y; v0.z *= g0.z; v0.w *= g0.w;
        v1.x *= g1.x; v1.y *= g1.y; v1.z *= g1.z; v1.w *= g1.w;
        out[(size_t)r  * CV + lane] = v0;
        out[(size_t)r2 * CV + lane] = v1;
    }
    if (r < n) {
        int b = bidx[r];
        float4 v = x[(size_t)r * CV + lane];
        float4 g = s_gate[b][lane];
        v.x *= g.x; v.y *= g.y; v.z *= g.z; v.w *= g.w;
        out[(size_t)r * CV + lane] = v;
    }
}

// ---------------------------------------------------------------------------
extern "C" void kernel_launch(void* const* d_in, const int* in_sizes, int n_in,
                              void* d_out, int out_size)
{
    const float* x    = (const float*)d_in[0];
    const int*   bidx = (const int*)d_in[1];
    const float* W1   = (const float*)d_in[2];
    const float* b1   = (const float*)d_in[3];
    const float* W2   = (const float*)d_in[4];
    const float* b2   = (const float*)d_in[5];
    float* out = (float*)d_out;

    int n = in_sizes[1];  // number of rows (batch_idx has N entries)
    int rows_per_block = (n + RED_BLOCKS - 1) / RED_BLOCKS;

    reduce_kernel<<<RED_BLOCKS, 256>>>((const float4*)x, bidx, n, rows_per_block);
    mlp_kernel<<<1, 256>>>(W1, b1, W2, b2);
    apply_kernel<<<APPLY_BLOCKS, 256>>>((const float4*)x, bidx, (float4*)out, n);
}

// round 13
// speedup vs baseline: 3.7352x; 1.0132x over previous
#include <cuda_runtime.h>
#include <math.h>

#define C 128
#define CV 32            // C/4 float4 per row
#define HID 8
#define NB 16

#define RED_BLOCKS 592   // R6/R12-measured optimum (55.6us, 38 regs)

// Scratch (no allocations allowed). Zero-initialized at load; mlp_kernel
// re-zeroes g_sums/g_counts after consuming them -> every call starts clean.
__device__ float g_sums[NB][C];
__device__ float g_counts[NB];
__device__ float g_gate[NB][C];

// ---------------------------------------------------------------------------
// 1) segment sum — EXACT R12 form (measured 55.6us, regs=38). Chunked,
//    ascending, branchless per-segment streaming (unroll 8, two accums).
// ---------------------------------------------------------------------------
__device__ __forceinline__ int lower_bound_idx(const int* __restrict__ bidx,
                                               int lo, int hi, int val) {
    while (lo < hi) {
        int mid = (lo + hi) >> 1;
        if (bidx[mid] < val) lo = mid + 1; else hi = mid;
    }
    return lo;
}

__global__ __launch_bounds__(256) void reduce_kernel(
    const float4* __restrict__ x, const int* __restrict__ bidx,
    int n, int rows_per_block)
{
    int row0 = blockIdx.x * rows_per_block;
    int row1 = row0 + rows_per_block;
    if (row1 > n) row1 = n;
    if (row0 >= row1) return;

    int warp = threadIdx.x >> 5;
    int lane = threadIdx.x & 31;

    int b_first = bidx[row0];
    int b_last  = bidx[row1 - 1];

    int seg_start = row0;
    for (int b = b_first; b <= b_last; b++) {
        int seg_end = (b == b_last) ? row1
                    : lower_bound_idx(bidx, seg_start, row1, b + 1);

        float4 accA = make_float4(0.f, 0.f, 0.f, 0.f);
        float4 accB = make_float4(0.f, 0.f, 0.f, 0.f);

        int r = seg_start + warp;
        for (; r + 56 < seg_end; r += 64) {
            float4 v0 = x[(size_t)(r)      * CV + lane];
            float4 v1 = x[(size_t)(r + 8)  * CV + lane];
            float4 v2 = x[(size_t)(r + 16) * CV + lane];
            float4 v3 = x[(size_t)(r + 24) * CV + lane];
            float4 v4 = x[(size_t)(r + 32) * CV + lane];
            float4 v5 = x[(size_t)(r + 40) * CV + lane];
            float4 v6 = x[(size_t)(r + 48) * CV + lane];
            float4 v7 = x[(size_t)(r + 56) * CV + lane];
            accA.x += v0.x; accA.y += v0.y; accA.z += v0.z; accA.w += v0.w;
            accB.x += v1.x; accB.y += v1.y; accB.z += v1.z; accB.w += v1.w;
            accA.x += v2.x; accA.y += v2.y; accA.z += v2.z; accA.w += v2.w;
            accB.x += v3.x; accB.y += v3.y; accB.z += v3.z; accB.w += v3.w;
            accA.x += v4.x; accA.y += v4.y; accA.z += v4.z; accA.w += v4.w;
            accB.x += v5.x; accB.y += v5.y; accB.z += v5.z; accB.w += v5.w;
            accA.x += v6.x; accA.y += v6.y; accA.z += v6.z; accA.w += v6.w;
            accB.x += v7.x; accB.y += v7.y; accB.z += v7.z; accB.w += v7.w;
        }
        for (; r < seg_end; r += 8) {
            float4 v = x[(size_t)r * CV + lane];
            accA.x += v.x; accA.y += v.y; accA.z += v.z; accA.w += v.w;
        }

        int seg_len = seg_end - seg_start;
        if (seg_len > 0) {
            float* dst = &g_sums[b][lane * 4];
            atomicAdd(dst + 0, accA.x + accB.x);
            atomicAdd(dst + 1, accA.y + accB.y);
            atomicAdd(dst + 2, accA.z + accB.z);
            atomicAdd(dst + 3, accA.w + accB.w);
            if (lane == 0 && warp == 0)
                atomicAdd(&g_counts[b], (float)seg_len);
        }
        seg_start = seg_end;
    }
}

// ---------------------------------------------------------------------------
// 2) tiny MLP (R9 fast version): 256 threads, weights cooperatively
//    preloaded vectorized. Re-zeroes accumulators for the next invocation.
// ---------------------------------------------------------------------------
__global__ __launch_bounds__(256) void mlp_kernel(
    const float* __restrict__ W1, const float* __restrict__ b1,
    const float* __restrict__ W2, const float* __restrict__ b2)
{
    __shared__ float sW1[C * HID];
    __shared__ float sW2[HID * C];
    __shared__ float s_b1[HID];
    __shared__ float s_b2[C];
    __shared__ float s_mean[NB][C];
    __shared__ float s_h[NB][HID];

    int t = threadIdx.x;  // 0..255

    for (int i = t; i < (C * HID) / 4; i += 256) {
        ((float4*)sW1)[i] = ((const float4*)W1)[i];
        ((float4*)sW2)[i] = ((const float4*)W2)[i];
    }
    if (t < HID) s_b1[t] = b1[t];
    if (t < C)   s_b2[t] = b2[t];
    for (int i = t; i < NB * C; i += 256) {
        int b = i / C;
        float cn = fmaxf(g_counts[b], 1.0f);
        ((float*)s_mean)[i] = ((const float*)g_sums)[i] / cn;
    }
    __syncthreads();

    // reset accumulators for the next invocation
    for (int i = t; i < NB * C; i += 256) ((float*)g_sums)[i] = 0.0f;
    if (t < NB) g_counts[t] = 0.0f;

    if (t < NB * HID) {                // 128 outputs: h[b][j]
        int b = t / HID, j = t % HID;
        float acc = s_b1[j];
        #pragma unroll 8
        for (int c = 0; c < C; c++) acc += s_mean[b][c] * sW1[c * HID + j];
        s_h[b][j] = fmaxf(acc, 0.0f);
    }
    __syncthreads();

    if (t < C) {                       // gate column c = t
        int c = t;
        float w2c[HID];
        #pragma unroll
        for (int j = 0; j < HID; j++) w2c[j] = sW2[j * C + c];
        float bias = s_b2[c];
        for (int b = 0; b < NB; b++) {
            float acc = bias;
            #pragma unroll
            for (int j = 0; j < HID; j++) acc += s_h[b][j] * w2c[j];
            g_gate[b][c] = 1.0f / (1.0f + expf(-acc));
        }
    }
}

// ---------------------------------------------------------------------------
// 3) apply gate — L2-reuse experiment (ISOLATED this time):
//    SAME 592-chunk mapping as reduce; each block walks its chunk DESCENDING
//    so its first reads hit the chunk tail that reduce touched last (still
//    L2-resident: ~126MB persists across launches, only L1 flushes).
//    PLAIN loads/stores (no __ldcs/__stcs — suspected cause of R6 regression).
//    Unroll-4 front-batched loads keeps in-flight bytes at parity with the
//    1184-block grid-stride version.
// ---------------------------------------------------------------------------
__global__ __launch_bounds__(256) void apply_kernel(
    const float4* __restrict__ x, const int* __restrict__ bidx,
    float4* __restrict__ out, int n, int rows_per_block)
{
    __shared__ float4 s_gate[NB][CV];  // 8 KB
    for (int i = threadIdx.x; i < NB * CV; i += blockDim.x)
        ((float4*)s_gate)[i] = ((const float4*)g_gate)[i];
    __syncthreads();

    int row0 = blockIdx.x * rows_per_block;
    int row1 = row0 + rows_per_block;
    if (row1 > n) row1 = n;
    if (row0 >= row1) return;

    int warp = threadIdx.x >> 5;
    int lane = threadIdx.x & 31;

    int r = row1 - 1 - warp;
    for (; r - 24 >= row0; r -= 32) {
        int r1 = r - 8, r2 = r - 16, r3 = r - 24;
        int b0 = bidx[r];
        int b1 = bidx[r1];
        int b2 = bidx[r2];
        int b3 = bidx[r3];
        float4 v0 = x[(size_t)r  * CV + lane];
        float4 v1 = x[(size_t)r1 * CV + lane];
        float4 v2 = x[(size_t)r2 * CV + lane];
        float4 v3 = x[(size_t)r3 * CV + lane];
        float4 g0 = s_gate[b0][lane];
        float4 g1 = s_gate[b1][lane];
        float4 g2 = s_gate[b2][lane];
        float4 g3 = s_gate[b3][lane];
        v0.x *= g0.x; v0.y *= g0.y; v0.z *= g0.z; v0.w *= g0.w;
        v1.x *= g1.x; v1.y *= g1.y; v1.z *= g1.z; v1.w *= g1.w;
        v2.x *= g2.x; v2.y *= g2.y; v2.z *= g2.z; v2.w *= g2.w;
        v3.x *= g3.x; v3.y *= g3.y; v3.z *= g3.z; v3.w *= g3.w;
        out[(size_t)r  * CV + lane] = v0;
        out[(size_t)r1 * CV + lane] = v1;
        out[(size_t)r2 * CV + lane] = v2;
        out[(size_t)r3 * CV + lane] = v3;
    }
    for (; r >= row0; r -= 8) {
        int b = bidx[r];
        float4 v = x[(size_t)r * CV + lane];
        float4 g = s_gate[b][lane];
        v.x *= g.x; v.y *= g.y; v.z *= g.z; v.w *= g.w;
        out[(size_t)r * CV + lane] = v;
    }
}

// ---------------------------------------------------------------------------
extern "C" void kernel_launch(void* const* d_in, const int* in_sizes, int n_in,
                              void* d_out, int out_size)
{
    const float* x    = (const float*)d_in[0];
    const int*   bidx = (const int*)d_in[1];
    const float* W1   = (const float*)d_in[2];
    const float* b1   = (const float*)d_in[3];
    const float* W2   = (const float*)d_in[4];
    const float* b2   = (const float*)d_in[5];
    float* out = (float*)d_out;

    int n = in_sizes[1];  // number of rows (batch_idx has N entries)
    int rows_per_block = (n + RED_BLOCKS - 1) / RED_BLOCKS;

    reduce_kernel<<<RED_BLOCKS, 256>>>((const float4*)x, bidx, n, rows_per_block);
    mlp_kernel<<<1, 256>>>(W1, b1, W2, b2);
    apply_kernel<<<RED_BLOCKS, 256>>>((const float4*)x, bidx, (float4*)out, n,
                                      rows_per_block);
}